// round 11
// baseline (speedup 1.0000x reference)
#include <cuda_runtime.h>
#include <cuda_bf16.h>
#include <math.h>

#define Bb 8
#define Nn 4096
#define Mm 2048
#define Dd 512
typedef unsigned u32;

// ---------------- scratch (bf16 packed words, 16B aligned) ----------------
__device__ __align__(16) u32 g_fh [(size_t)Bb * Nn * (Dd / 2)];  // feat rows bf16
__device__ __align__(16) u32 g_fTh[(size_t)Bb * Dd * (Nn / 2)];  // feat^T bf16
__device__ __align__(16) u32 g_wt [(size_t)Dd * (Dd / 2)];       // W^T rows bf16
__device__ __align__(16) u32 g_tnh[(size_t)Mm * (Dd / 2)];       // tn rows bf16
__device__ __align__(16) u32 g_fnh[(size_t)Bb * Nn * (Dd / 2)];  // f1 (unnormalized) bf16
__device__ __align__(16) u32 g_eth[(size_t)Bb * Mm * (Nn / 2)];  // e^T: [b][m][(n,n+1)]
__device__ float g_s[Bb * Mm];   // softmax denominators
__device__ float g_rn[Bb * Nn];  // per-row |f1|^2

__device__ __forceinline__ u32 pk2(float lo, float hi) {
    __nv_bfloat162 h = __floats2bfloat162_rn(lo, hi);
    return *(u32*)&h;
}
__device__ __forceinline__ u32 s2u(const void* p) {
    return (u32)__cvta_generic_to_shared(p);
}
__device__ __forceinline__ void cpa16(u32 saddr, const void* g) {
    asm volatile("cp.async.cg.shared.global [%0], [%1], 16;" :: "r"(saddr), "l"(g));
}
#define CP_COMMIT asm volatile("cp.async.commit_group;" ::: "memory")
#define CP_WAIT2 asm volatile("cp.async.wait_group 2;" ::: "memory")
__device__ __forceinline__ void ldsm4(u32& r0, u32& r1, u32& r2, u32& r3, u32 addr) {
    asm volatile("ldmatrix.sync.aligned.m8n8.x4.shared.b16 {%0,%1,%2,%3}, [%4];"
                 : "=r"(r0), "=r"(r1), "=r"(r2), "=r"(r3) : "r"(addr));
}
__device__ __forceinline__ void mma_bf16(float& d0, float& d1, float& d2, float& d3,
                                         u32 a0, u32 a1, u32 a2, u32 a3,
                                         u32 b0, u32 b1) {
    asm volatile(
        "mma.sync.aligned.m16n8k16.row.col.f32.bf16.bf16.f32 "
        "{%0,%1,%2,%3}, {%4,%5,%6,%7}, {%8,%9}, {%0,%1,%2,%3};"
        : "+f"(d0), "+f"(d1), "+f"(d2), "+f"(d3)
        : "r"(a0), "r"(a1), "r"(a2), "r"(a3), "r"(b0), "r"(b1));
}

// ---------------- small kernels ----------------
__global__ void k_zero() {
    int i = blockIdx.x * 256 + threadIdx.x;
    if (i < Bb * Mm) g_s[i] = 0.f;
    if (i < Bb * Nn) g_rn[i] = 0.f;
}

__global__ void k_text(const float* __restrict__ text, float* __restrict__ out) {
    int m = blockIdx.x, tid = threadIdx.x;
    const float4* t1 = (const float4*)(text + (size_t)Mm * Dd + (size_t)m * Dd);
    float4 v = t1[tid];
    float ss = v.x * v.x + v.y * v.y + v.z * v.z + v.w * v.w;
#pragma unroll
    for (int o = 16; o > 0; o >>= 1) ss += __shfl_xor_sync(0xffffffffu, ss, o);
    __shared__ float ws[4];
    if ((tid & 31) == 0) ws[tid >> 5] = ss;
    __syncthreads();
    float inv = 1.f / fmaxf(sqrtf(ws[0] + ws[1] + ws[2] + ws[3]), 1e-8f);
    *(uint2*)(g_tnh + (size_t)m * (Dd / 2) + tid * 2) =
        make_uint2(pk2(v.x * inv, v.y * inv), pk2(v.z * inv, v.w * inv));
#pragma unroll
    for (int b = 0; b < Bb; b++) {
        float4* o = (float4*)(out + ((size_t)(b * Mm + m)) * (2 * Dd) + Dd);
        o[tid] = v;
    }
}

// features -> g_fh (row-major bf16) + g_fTh (transpose-pack)
__global__ void k_prepfeat(const float* __restrict__ feat) {
    __shared__ float sm[64][65];
    int b = blockIdx.z, d0 = blockIdx.y * 64, n0 = blockIdx.x * 64;
    int t = threadIdx.x;
    int lr = t >> 4, lc = (t & 15) * 4;
#pragma unroll
    for (int r = 0; r < 4; r++) {
        int n = n0 + lr + r * 16;
        float4 v = *(const float4*)(feat + ((size_t)b * Nn + n) * Dd + d0 + lc);
        sm[lr + r * 16][lc + 0] = v.x;
        sm[lr + r * 16][lc + 1] = v.y;
        sm[lr + r * 16][lc + 2] = v.z;
        sm[lr + r * 16][lc + 3] = v.w;
        *(uint2*)(g_fh + ((size_t)b * Nn + n) * (Dd / 2) + (d0 + lc) / 2) =
            make_uint2(pk2(v.x, v.y), pk2(v.z, v.w));
    }
    __syncthreads();
    int d = t >> 2, npb = (t & 3) * 8;
    u32 w[8];
#pragma unroll
    for (int j = 0; j < 8; j++)
        w[j] = pk2(sm[2 * (npb + j)][d], sm[2 * (npb + j) + 1][d]);
    u32* dst = g_fTh + ((size_t)b * Dd + d0 + d) * (Nn / 2) + n0 / 2 + npb;
    *(uint4*)dst = make_uint4(w[0], w[1], w[2], w[3]);
    *(uint4*)(dst + 4) = make_uint4(w[4], w[5], w[6], w[7]);
}

// W[d][e] -> g_wt[e][(d,d+1)]
__global__ void k_prepW(const float* __restrict__ W) {
    __shared__ float sm[64][65];
    int d0 = blockIdx.y * 64, e0 = blockIdx.x * 64;
    int t = threadIdx.x;
    int lr = t >> 4, lc = (t & 15) * 4;
#pragma unroll
    for (int r = 0; r < 4; r++) {
        float4 v = *(const float4*)(W + (size_t)(d0 + lr + r * 16) * Dd + e0 + lc);
        sm[lr + r * 16][lc + 0] = v.x;
        sm[lr + r * 16][lc + 1] = v.y;
        sm[lr + r * 16][lc + 2] = v.z;
        sm[lr + r * 16][lc + 3] = v.w;
    }
    __syncthreads();
    int e = t >> 2, dpb = (t & 3) * 8;
    u32 w[8];
#pragma unroll
    for (int j = 0; j < 8; j++)
        w[j] = pk2(sm[2 * (dpb + j)][e], sm[2 * (dpb + j) + 1][e]);
    u32* dst = g_wt + (size_t)(e0 + e) * (Dd / 2) + d0 / 2 + dpb;
    *(uint4*)dst = make_uint4(w[0], w[1], w[2], w[3]);
    *(uint4*)(dst + 4) = make_uint4(w[4], w[5], w[6], w[7]);
}

// ==== GEMM: block 128x256, 256 thr, warp tile 64x64, 4 stages of k32 ====
// smem rows = 8 words (32B), chunk swizzle: phys = c ^ ((row>>2)&1)
// stage = two k16 sub-tiles: A 8KB (2x4KB), B 16KB (2x8KB). 96KB total.

__device__ __forceinline__ void ldA(u32 dst, const u32* src, size_t ldw, int kw, int tid) {
    int r = tid >> 1, c = tid & 1;
    cpa16(dst + (u32)(r * 32 + ((c ^ ((r >> 2) & 1)) * 16)),
          src + (size_t)r * ldw + kw + c * 4);
}
__device__ __forceinline__ void ldB(u32 dst, const u32* src, size_t ldw, int kw, int tid) {
    int r0 = tid >> 1, c = tid & 1;
#pragma unroll
    for (int i = 0; i < 2; i++) {
        int r = r0 + i * 128;
        cpa16(dst + (u32)(r * 32 + ((c ^ ((r >> 2) & 1)) * 16)),
              src + (size_t)r * ldw + kw + c * 4);
    }
}
// one k32 stage = two k16 sub-tiles
__device__ __forceinline__ void ldA32(u32 dst, const u32* src, size_t ldw, int kw, int tid) {
    ldA(dst, src, ldw, kw, tid);
    ldA(dst + 4096, src, ldw, kw + 8, tid);
}
__device__ __forceinline__ void ldB32(u32 dst, const u32* src, size_t ldw, int kw, int tid) {
    ldB(dst, src, ldw, kw, tid);
    ldB(dst + 8192, src, ldw, kw + 8, tid);
}

#define GEMM_DECLS                                                          \
    __shared__ __align__(16) u32 sA[4][2048], sB[4][4096];                  \
    u32 sAu = s2u(sA), sBu = s2u(sB);                                       \
    int tid = threadIdx.x, lane = tid & 31, warp = tid >> 5;                \
    int wm = warp >> 2, wn = warp & 3;                                      \
    int lg = lane >> 2, lt = lane & 3;                                      \
    int rowA = wm * 64 + (lane & 15);                                       \
    u32 aoff = (u32)(rowA * 32 + (((lane >> 4) ^ ((rowA >> 2) & 1)) * 16)); \
    int rowB = wn * 64 + (lane & 7) + ((lane >> 4) << 3);                   \
    u32 boff = (u32)(rowB * 32 + ((((lane >> 3) & 1) ^ ((rowB >> 2) & 1)) * 16)); \
    float acc[4][8][4];                                                     \
    _Pragma("unroll") for (int i = 0; i < 4; i++)                           \
    _Pragma("unroll") for (int j = 0; j < 8; j++)                           \
    _Pragma("unroll") for (int r = 0; r < 4; r++) acc[i][j][r] = 0.f;

#define COMPUTE16(pA, pB) {                                                 \
    u32 af[4][4], bq[4][4];                                                 \
    _Pragma("unroll") for (int mt = 0; mt < 4; mt++)                        \
        ldsm4(af[mt][0], af[mt][1], af[mt][2], af[mt][3],                   \
              sAu + (pA) + aoff + mt * 512);                                \
    _Pragma("unroll") for (int pq = 0; pq < 4; pq++)                        \
        ldsm4(bq[pq][0], bq[pq][1], bq[pq][2], bq[pq][3],                   \
              sBu + (pB) + boff + pq * 512);                                \
    _Pragma("unroll") for (int mt = 0; mt < 4; mt++)                        \
        _Pragma("unroll") for (int nt = 0; nt < 8; nt++)                    \
            mma_bf16(acc[mt][nt][0], acc[mt][nt][1],                        \
                     acc[mt][nt][2], acc[mt][nt][3],                        \
                     af[mt][0], af[mt][1], af[mt][2], af[mt][3],            \
                     bq[nt >> 1][(nt & 1) * 2], bq[nt >> 1][(nt & 1) * 2 + 1]); }

// 4 stages of k32, prefetch 3 ahead, wait_group 2, one sync per k32.
// S2 = number of k32 stages.
#define MAINLOOP(Asrc, Aldw, Bsrc, Bldw, S2)                                \
    _Pragma("unroll") for (int st = 0; st < 3; st++) {                      \
        ldA32(sAu + st * 8192, (Asrc), (Aldw), st * 16, tid);               \
        ldB32(sBu + st * 16384, (Bsrc), (Bldw), st * 16, tid);              \
        CP_COMMIT;                                                          \
    }                                                                       \
    for (int s = 0; s < (S2); s++) {                                        \
        int p = s & 3;                                                      \
        CP_WAIT2; __syncthreads();                                          \
        COMPUTE16(p * 8192, p * 16384)                                      \
        COMPUTE16(p * 8192 + 4096, p * 16384 + 8192)                        \
        int f = s + 3;                                                      \
        if (f < (S2)) {                                                     \
            int q = f & 3;                                                  \
            ldA32(sAu + q * 8192, (Asrc), (Aldw), f * 16, tid);             \
            ldB32(sBu + q * 16384, (Bsrc), (Bldw), f * 16, tid);            \
        }                                                                   \
        CP_COMMIT;                                                          \
    }

// ---------------- K2: f1 = feat @ W + b -> g_fnh (+ row |f1|^2) ----------
__global__ __launch_bounds__(256, 1)
void k_linear(const float* __restrict__ bias) {
    GEMM_DECLS
    int m0 = blockIdx.y * 128;  // over B*N
    int e0 = blockIdx.x * 256;  // over Dd
    const u32* Asrc = g_fh + (size_t)m0 * (Dd / 2);
    const u32* Bsrc = g_wt + (size_t)e0 * (Dd / 2);
    MAINLOOP(Asrc, Dd / 2, Bsrc, Dd / 2, 16)
    float rs[4][2];
#pragma unroll
    for (int mt = 0; mt < 4; mt++) { rs[mt][0] = 0.f; rs[mt][1] = 0.f; }
#pragma unroll
    for (int mt = 0; mt < 4; mt++) {
        int row = m0 + wm * 64 + mt * 16 + lg;
#pragma unroll
        for (int nt = 0; nt < 8; nt++) {
            int col = e0 + wn * 64 + nt * 8 + lt * 2;
            float b0 = __ldg(bias + col), b1 = __ldg(bias + col + 1);
            float f0 = acc[mt][nt][0] + b0, f1 = acc[mt][nt][1] + b1;
            float f2 = acc[mt][nt][2] + b0, f3 = acc[mt][nt][3] + b1;
            g_fnh[((size_t)row * Dd + col) >> 1] = pk2(f0, f1);
            g_fnh[((size_t)(row + 8) * Dd + col) >> 1] = pk2(f2, f3);
            rs[mt][0] += f0 * f0 + f1 * f1;
            rs[mt][1] += f2 * f2 + f3 * f3;
        }
    }
#pragma unroll
    for (int mt = 0; mt < 4; mt++)
#pragma unroll
        for (int r = 0; r < 2; r++) {
            float v = rs[mt][r];
            v += __shfl_xor_sync(0xffffffffu, v, 1);
            v += __shfl_xor_sync(0xffffffffu, v, 2);
            if (lt == 0)
                atomicAdd(&g_rn[m0 + wm * 64 + mt * 16 + lg + r * 8], v);
        }
}

// ---------------- K3: e^T = exp(tn @ f1^T * invnorm) -> g_eth; row sums ---
__global__ __launch_bounds__(256, 1)
void k_sim() {
    GEMM_DECLS
    __shared__ float sc[256];
    int b = blockIdx.z;
    int m0 = blockIdx.y * 128;  // over Mm
    int n0 = blockIdx.x * 256;  // over Nn
    const u32* Asrc = g_tnh + (size_t)m0 * (Dd / 2);
    const u32* Bsrc = g_fnh + ((size_t)b * Nn + n0) * (Dd / 2);
    MAINLOOP(Asrc, Dd / 2, Bsrc, Dd / 2, 16)
    sc[tid] = 1.f / fmaxf(sqrtf(g_rn[b * Nn + n0 + tid]), 1e-8f);
    __syncthreads();
    float rs[4][2];
#pragma unroll
    for (int mt = 0; mt < 4; mt++) { rs[mt][0] = 0.f; rs[mt][1] = 0.f; }
#pragma unroll
    for (int mt = 0; mt < 4; mt++) {
        int m = m0 + wm * 64 + mt * 16 + lg;
#pragma unroll
        for (int nt = 0; nt < 8; nt++) {
            int cl = wn * 64 + nt * 8 + lt * 2;  // col within block
            float i0 = sc[cl], i1 = sc[cl + 1];
            float e0 = __expf(acc[mt][nt][0] * i0);
            float e1 = __expf(acc[mt][nt][1] * i1);
            float e2 = __expf(acc[mt][nt][2] * i0);
            float e3 = __expf(acc[mt][nt][3] * i1);
            int nw = (n0 + cl) >> 1;
            g_eth[((size_t)b * Mm + m) * (Nn / 2) + nw] = pk2(e0, e1);
            g_eth[((size_t)b * Mm + m + 8) * (Nn / 2) + nw] = pk2(e2, e3);
            rs[mt][0] += e0 + e1;
            rs[mt][1] += e2 + e3;
        }
    }
#pragma unroll
    for (int mt = 0; mt < 4; mt++)
#pragma unroll
        for (int r = 0; r < 2; r++) {
            float v = rs[mt][r];
            v += __shfl_xor_sync(0xffffffffu, v, 1);
            v += __shfl_xor_sync(0xffffffffu, v, 2);
            if (lt == 0)
                atomicAdd(&g_s[b * Mm + m0 + wm * 64 + mt * 16 + lg + r * 8], v);
        }
}

// ---------------- K4: out[...,:512] = (e @ feat) / s ----------------------
__global__ __launch_bounds__(256, 1)
void k_out(float* __restrict__ out) {
    GEMM_DECLS
    int b = blockIdx.z;
    int m0 = blockIdx.y * 128;  // over Mm
    int d0 = blockIdx.x * 256;  // over Dd
    const u32* Asrc = g_eth + ((size_t)b * Mm + m0) * (Nn / 2);
    const u32* Bsrc = g_fTh + ((size_t)b * Dd + d0) * (Nn / 2);
    MAINLOOP(Asrc, Nn / 2, Bsrc, Nn / 2, Nn / 32)
#pragma unroll
    for (int mt = 0; mt < 4; mt++) {
        int row = m0 + wm * 64 + mt * 16 + lg;
        float i0 = 1.f / g_s[b * Mm + row];
        float i1 = 1.f / g_s[b * Mm + row + 8];
#pragma unroll
        for (int nt = 0; nt < 8; nt++) {
            int col = d0 + wn * 64 + nt * 8 + lt * 2;
            *(float2*)(out + ((size_t)(b * Mm + row)) * (2 * Dd) + col) =
                make_float2(acc[mt][nt][0] * i0, acc[mt][nt][1] * i0);
            *(float2*)(out + ((size_t)(b * Mm + row + 8)) * (2 * Dd) + col) =
                make_float2(acc[mt][nt][2] * i1, acc[mt][nt][3] * i1);
        }
    }
}

// ---------------- launch ----------------
extern "C" void kernel_launch(void* const* d_in, const int* in_sizes, int n_in,
                              void* d_out, int out_size) {
    const float* features = (const float*)d_in[0];
    const float* text     = (const float*)d_in[1];
    const float* W        = (const float*)d_in[2];
    const float* bias     = (const float*)d_in[3];
    float* out = (float*)d_out;

    k_zero<<<(Bb * Nn + 255) / 256, 256>>>();
    k_text<<<Mm, 128>>>(text, out);
    k_prepW<<<dim3(Dd / 64, Dd / 64), 256>>>(W);
    k_prepfeat<<<dim3(Nn / 64, Dd / 64, Bb), 256>>>(features);
    k_linear<<<dim3(Dd / 256, (Bb * Nn) / 128), 256>>>(bias);
    k_sim<<<dim3(Nn / 256, Mm / 128, Bb), 256>>>();
    k_out<<<dim3(Dd / 256, Mm / 128, Bb), 256>>>(out);
}

// round 12
// speedup vs baseline: 1.0854x; 1.0854x over previous
#include <cuda_runtime.h>
#include <cuda_bf16.h>
#include <math.h>

#define Bb 8
#define Nn 4096
#define Mm 2048
#define Dd 512
typedef unsigned u32;

// ---------------- scratch (bf16 packed words, 16B aligned) ----------------
__device__ __align__(16) u32 g_fh [(size_t)Bb * Nn * (Dd / 2)];  // feat rows bf16
__device__ __align__(16) u32 g_fTh[(size_t)Bb * Dd * (Nn / 2)];  // feat^T bf16
__device__ __align__(16) u32 g_wt [(size_t)Dd * (Dd / 2)];       // W^T rows bf16
__device__ __align__(16) u32 g_tnh[(size_t)Mm * (Dd / 2)];       // tn rows bf16
__device__ __align__(16) u32 g_fnh[(size_t)Bb * Nn * (Dd / 2)];  // f1 (unnormalized) bf16
__device__ __align__(16) u32 g_eth[(size_t)Bb * Mm * (Nn / 2)];  // e^T: [b][m][(n,n+1)]
__device__ float g_s[Bb * Mm];   // softmax denominators
__device__ float g_rn[Bb * Nn];  // per-row |f1|^2

__device__ __forceinline__ u32 pk2(float lo, float hi) {
    __nv_bfloat162 h = __floats2bfloat162_rn(lo, hi);
    return *(u32*)&h;
}
__device__ __forceinline__ u32 s2u(const void* p) {
    return (u32)__cvta_generic_to_shared(p);
}
__device__ __forceinline__ void cpa16(u32 saddr, const void* g) {
    asm volatile("cp.async.cg.shared.global [%0], [%1], 16;" :: "r"(saddr), "l"(g));
}
#define CP_COMMIT asm volatile("cp.async.commit_group;" ::: "memory")
#define CP_WAIT2 asm volatile("cp.async.wait_group 2;" ::: "memory")
__device__ __forceinline__ void ldsm4(u32& r0, u32& r1, u32& r2, u32& r3, u32 addr) {
    asm volatile("ldmatrix.sync.aligned.m8n8.x4.shared.b16 {%0,%1,%2,%3}, [%4];"
                 : "=r"(r0), "=r"(r1), "=r"(r2), "=r"(r3) : "r"(addr));
}
__device__ __forceinline__ void mma_bf16(float& d0, float& d1, float& d2, float& d3,
                                         u32 a0, u32 a1, u32 a2, u32 a3,
                                         u32 b0, u32 b1) {
    asm volatile(
        "mma.sync.aligned.m16n8k16.row.col.f32.bf16.bf16.f32 "
        "{%0,%1,%2,%3}, {%4,%5,%6,%7}, {%8,%9}, {%0,%1,%2,%3};"
        : "+f"(d0), "+f"(d1), "+f"(d2), "+f"(d3)
        : "r"(a0), "r"(a1), "r"(a2), "r"(a3), "r"(b0), "r"(b1));
}

// ---------------- small kernels ----------------
__global__ void k_zero() {
    int i = blockIdx.x * 256 + threadIdx.x;
    if (i < Bb * Mm) g_s[i] = 0.f;
    if (i < Bb * Nn) g_rn[i] = 0.f;
}

__global__ void k_text(const float* __restrict__ text, float* __restrict__ out) {
    int m = blockIdx.x, tid = threadIdx.x;
    const float4* t1 = (const float4*)(text + (size_t)Mm * Dd + (size_t)m * Dd);
    float4 v = t1[tid];
    float ss = v.x * v.x + v.y * v.y + v.z * v.z + v.w * v.w;
#pragma unroll
    for (int o = 16; o > 0; o >>= 1) ss += __shfl_xor_sync(0xffffffffu, ss, o);
    __shared__ float ws[4];
    if ((tid & 31) == 0) ws[tid >> 5] = ss;
    __syncthreads();
    float inv = 1.f / fmaxf(sqrtf(ws[0] + ws[1] + ws[2] + ws[3]), 1e-8f);
    *(uint2*)(g_tnh + (size_t)m * (Dd / 2) + tid * 2) =
        make_uint2(pk2(v.x * inv, v.y * inv), pk2(v.z * inv, v.w * inv));
#pragma unroll
    for (int b = 0; b < Bb; b++) {
        float4* o = (float4*)(out + ((size_t)(b * Mm + m)) * (2 * Dd) + Dd);
        o[tid] = v;
    }
}

// features -> g_fh (row-major bf16) + g_fTh (transpose-pack)
__global__ void k_prepfeat(const float* __restrict__ feat) {
    __shared__ float sm[64][65];
    int b = blockIdx.z, d0 = blockIdx.y * 64, n0 = blockIdx.x * 64;
    int t = threadIdx.x;
    int lr = t >> 4, lc = (t & 15) * 4;
#pragma unroll
    for (int r = 0; r < 4; r++) {
        int n = n0 + lr + r * 16;
        float4 v = *(const float4*)(feat + ((size_t)b * Nn + n) * Dd + d0 + lc);
        sm[lr + r * 16][lc + 0] = v.x;
        sm[lr + r * 16][lc + 1] = v.y;
        sm[lr + r * 16][lc + 2] = v.z;
        sm[lr + r * 16][lc + 3] = v.w;
        *(uint2*)(g_fh + ((size_t)b * Nn + n) * (Dd / 2) + (d0 + lc) / 2) =
            make_uint2(pk2(v.x, v.y), pk2(v.z, v.w));
    }
    __syncthreads();
    int d = t >> 2, npb = (t & 3) * 8;
    u32 w[8];
#pragma unroll
    for (int j = 0; j < 8; j++)
        w[j] = pk2(sm[2 * (npb + j)][d], sm[2 * (npb + j) + 1][d]);
    u32* dst = g_fTh + ((size_t)b * Dd + d0 + d) * (Nn / 2) + n0 / 2 + npb;
    *(uint4*)dst = make_uint4(w[0], w[1], w[2], w[3]);
    *(uint4*)(dst + 4) = make_uint4(w[4], w[5], w[6], w[7]);
}

// W[d][e] -> g_wt[e][(d,d+1)]
__global__ void k_prepW(const float* __restrict__ W) {
    __shared__ float sm[64][65];
    int d0 = blockIdx.y * 64, e0 = blockIdx.x * 64;
    int t = threadIdx.x;
    int lr = t >> 4, lc = (t & 15) * 4;
#pragma unroll
    for (int r = 0; r < 4; r++) {
        float4 v = *(const float4*)(W + (size_t)(d0 + lr + r * 16) * Dd + e0 + lc);
        sm[lr + r * 16][lc + 0] = v.x;
        sm[lr + r * 16][lc + 1] = v.y;
        sm[lr + r * 16][lc + 2] = v.z;
        sm[lr + r * 16][lc + 3] = v.w;
    }
    __syncthreads();
    int e = t >> 2, dpb = (t & 3) * 8;
    u32 w[8];
#pragma unroll
    for (int j = 0; j < 8; j++)
        w[j] = pk2(sm[2 * (dpb + j)][e], sm[2 * (dpb + j) + 1][e]);
    u32* dst = g_wt + (size_t)(e0 + e) * (Dd / 2) + d0 / 2 + dpb;
    *(uint4*)dst = make_uint4(w[0], w[1], w[2], w[3]);
    *(uint4*)(dst + 4) = make_uint4(w[4], w[5], w[6], w[7]);
}

// ==== GEMM: block 128x128, 256 thr (8 warps 2x4), warp tile 64x32, 2 CTAs/SM ====
// smem rows = 8 words (32B), chunk swizzle: phys = c ^ ((row>>2)&1)
// stage: A 4KB + B 4KB; 4 stages (32KB/CTA), 1 sync/iter, wait_group 2.

__device__ __forceinline__ void ldT(u32 dst, const u32* src, size_t ldw, int kw, int tid) {
    int r = tid >> 1, c = tid & 1;
    cpa16(dst + (u32)(r * 32 + ((c ^ ((r >> 2) & 1)) * 16)),
          src + (size_t)r * ldw + kw + c * 4);
}

#define GEMM_DECLS                                                          \
    __shared__ __align__(16) u32 sA[4][1024], sB[4][1024];                  \
    u32 sAu = s2u(sA), sBu = s2u(sB);                                       \
    int tid = threadIdx.x, lane = tid & 31, warp = tid >> 5;                \
    int wm = warp >> 2, wn = warp & 3;                                      \
    int lg = lane >> 2, lt = lane & 3;                                      \
    int rowA = wm * 64 + (lane & 15);                                       \
    u32 aoff = (u32)(rowA * 32 + (((lane >> 4) ^ ((rowA >> 2) & 1)) * 16)); \
    int rowB = wn * 32 + (lane & 7) + ((lane >> 4) << 3);                   \
    u32 boff = (u32)(rowB * 32 + ((((lane >> 3) & 1) ^ ((rowB >> 2) & 1)) * 16)); \
    float acc[4][4][4];                                                     \
    _Pragma("unroll") for (int i = 0; i < 4; i++)                           \
    _Pragma("unroll") for (int j = 0; j < 4; j++)                           \
    _Pragma("unroll") for (int r = 0; r < 4; r++) acc[i][j][r] = 0.f;

#define COMPUTE16(pA, pB) {                                                 \
    u32 af[4][4], bq[2][4];                                                 \
    _Pragma("unroll") for (int mt = 0; mt < 4; mt++)                        \
        ldsm4(af[mt][0], af[mt][1], af[mt][2], af[mt][3],                   \
              sAu + (pA) + aoff + mt * 512);                                \
    _Pragma("unroll") for (int pq = 0; pq < 2; pq++)                        \
        ldsm4(bq[pq][0], bq[pq][1], bq[pq][2], bq[pq][3],                   \
              sBu + (pB) + boff + pq * 512);                                \
    _Pragma("unroll") for (int mt = 0; mt < 4; mt++)                        \
        _Pragma("unroll") for (int nt = 0; nt < 4; nt++)                    \
            mma_bf16(acc[mt][nt][0], acc[mt][nt][1],                        \
                     acc[mt][nt][2], acc[mt][nt][3],                        \
                     af[mt][0], af[mt][1], af[mt][2], af[mt][3],            \
                     bq[nt >> 1][(nt & 1) * 2], bq[nt >> 1][(nt & 1) * 2 + 1]); }

// 4-stage pipeline, single __syncthreads per iter, wait_group 2 (round-8 proven).
#define MAINLOOP(Asrc, Aldw, Bsrc, Bldw, S)                                 \
    _Pragma("unroll") for (int st = 0; st < 3; st++) {                      \
        ldT(sAu + st * 4096, (Asrc), (Aldw), st * 8, tid);                  \
        ldT(sBu + st * 4096, (Bsrc), (Bldw), st * 8, tid);                  \
        CP_COMMIT;                                                          \
    }                                                                       \
    for (int s = 0; s < (S); s++) {                                         \
        int p = s & 3;                                                      \
        CP_WAIT2; __syncthreads();                                          \
        COMPUTE16(p * 4096, p * 4096)                                       \
        int f = s + 3;                                                      \
        if (f < (S)) {                                                      \
            int q = f & 3;                                                  \
            ldT(sAu + q * 4096, (Asrc), (Aldw), f * 8, tid);                \
            ldT(sBu + q * 4096, (Bsrc), (Bldw), f * 8, tid);                \
        }                                                                   \
        CP_COMMIT;                                                          \
    }

// ---------------- K2: f1 = feat @ W + b -> g_fnh (+ row |f1|^2) ----------
__global__ __launch_bounds__(256, 2)
void k_linear(const float* __restrict__ bias) {
    GEMM_DECLS
    int m0 = blockIdx.y * 128;  // over B*N
    int e0 = blockIdx.x * 128;  // over Dd
    const u32* Asrc = g_fh + (size_t)m0 * (Dd / 2);
    const u32* Bsrc = g_wt + (size_t)e0 * (Dd / 2);
    MAINLOOP(Asrc, Dd / 2, Bsrc, Dd / 2, 32)
    float rs[4][2];
#pragma unroll
    for (int mt = 0; mt < 4; mt++) { rs[mt][0] = 0.f; rs[mt][1] = 0.f; }
#pragma unroll
    for (int mt = 0; mt < 4; mt++) {
        int row = m0 + wm * 64 + mt * 16 + lg;
#pragma unroll
        for (int nt = 0; nt < 4; nt++) {
            int col = e0 + wn * 32 + nt * 8 + lt * 2;
            float b0 = __ldg(bias + col), b1 = __ldg(bias + col + 1);
            float f0 = acc[mt][nt][0] + b0, f1 = acc[mt][nt][1] + b1;
            float f2 = acc[mt][nt][2] + b0, f3 = acc[mt][nt][3] + b1;
            g_fnh[((size_t)row * Dd + col) >> 1] = pk2(f0, f1);
            g_fnh[((size_t)(row + 8) * Dd + col) >> 1] = pk2(f2, f3);
            rs[mt][0] += f0 * f0 + f1 * f1;
            rs[mt][1] += f2 * f2 + f3 * f3;
        }
    }
#pragma unroll
    for (int mt = 0; mt < 4; mt++)
#pragma unroll
        for (int r = 0; r < 2; r++) {
            float v = rs[mt][r];
            v += __shfl_xor_sync(0xffffffffu, v, 1);
            v += __shfl_xor_sync(0xffffffffu, v, 2);
            if (lt == 0)
                atomicAdd(&g_rn[m0 + wm * 64 + mt * 16 + lg + r * 8], v);
        }
}

// ---------------- K3: e^T = exp(tn @ f1^T * invnorm) -> g_eth; row sums ---
__global__ __launch_bounds__(256, 2)
void k_sim() {
    GEMM_DECLS
    __shared__ float sc[128];
    int b = blockIdx.z;
    int m0 = blockIdx.y * 128;  // over Mm
    int n0 = blockIdx.x * 128;  // over Nn
    const u32* Asrc = g_tnh + (size_t)m0 * (Dd / 2);
    const u32* Bsrc = g_fnh + ((size_t)b * Nn + n0) * (Dd / 2);
    MAINLOOP(Asrc, Dd / 2, Bsrc, Dd / 2, 32)
    if (tid < 128)
        sc[tid] = 1.f / fmaxf(sqrtf(g_rn[b * Nn + n0 + tid]), 1e-8f);
    __syncthreads();
    float rs[4][2];
#pragma unroll
    for (int mt = 0; mt < 4; mt++) { rs[mt][0] = 0.f; rs[mt][1] = 0.f; }
#pragma unroll
    for (int mt = 0; mt < 4; mt++) {
        int m = m0 + wm * 64 + mt * 16 + lg;
#pragma unroll
        for (int nt = 0; nt < 4; nt++) {
            int cl = wn * 32 + nt * 8 + lt * 2;  // col within block
            float i0 = sc[cl], i1 = sc[cl + 1];
            float e0 = __expf(acc[mt][nt][0] * i0);
            float e1 = __expf(acc[mt][nt][1] * i1);
            float e2 = __expf(acc[mt][nt][2] * i0);
            float e3 = __expf(acc[mt][nt][3] * i1);
            int nw = (n0 + cl) >> 1;
            g_eth[((size_t)b * Mm + m) * (Nn / 2) + nw] = pk2(e0, e1);
            g_eth[((size_t)b * Mm + m + 8) * (Nn / 2) + nw] = pk2(e2, e3);
            rs[mt][0] += e0 + e1;
            rs[mt][1] += e2 + e3;
        }
    }
#pragma unroll
    for (int mt = 0; mt < 4; mt++)
#pragma unroll
        for (int r = 0; r < 2; r++) {
            float v = rs[mt][r];
            v += __shfl_xor_sync(0xffffffffu, v, 1);
            v += __shfl_xor_sync(0xffffffffu, v, 2);
            if (lt == 0)
                atomicAdd(&g_s[b * Mm + m0 + wm * 64 + mt * 16 + lg + r * 8], v);
        }
}

// ---------------- K4: out[...,:512] = (e @ feat) / s ----------------------
__global__ __launch_bounds__(256, 2)
void k_out(float* __restrict__ out) {
    GEMM_DECLS
    int b = blockIdx.z;
    int m0 = blockIdx.x * 128;  // over Mm (x-fastest: share B tile in L2)
    int d0 = blockIdx.y * 128;  // over Dd
    const u32* Asrc = g_eth + ((size_t)b * Mm + m0) * (Nn / 2);
    const u32* Bsrc = g_fTh + ((size_t)b * Dd + d0) * (Nn / 2);
    MAINLOOP(Asrc, Nn / 2, Bsrc, Nn / 2, Nn / 16)
#pragma unroll
    for (int mt = 0; mt < 4; mt++) {
        int row = m0 + wm * 64 + mt * 16 + lg;
        float i0 = 1.f / g_s[b * Mm + row];
        float i1 = 1.f / g_s[b * Mm + row + 8];
#pragma unroll
        for (int nt = 0; nt < 4; nt++) {
            int col = d0 + wn * 32 + nt * 8 + lt * 2;
            *(float2*)(out + ((size_t)(b * Mm + row)) * (2 * Dd) + col) =
                make_float2(acc[mt][nt][0] * i0, acc[mt][nt][1] * i0);
            *(float2*)(out + ((size_t)(b * Mm + row + 8)) * (2 * Dd) + col) =
                make_float2(acc[mt][nt][2] * i1, acc[mt][nt][3] * i1);
        }
    }
}

// ---------------- launch ----------------
extern "C" void kernel_launch(void* const* d_in, const int* in_sizes, int n_in,
                              void* d_out, int out_size) {
    const float* features = (const float*)d_in[0];
    const float* text     = (const float*)d_in[1];
    const float* W        = (const float*)d_in[2];
    const float* bias     = (const float*)d_in[3];
    float* out = (float*)d_out;

    k_zero<<<(Bb * Nn + 255) / 256, 256>>>();
    k_text<<<Mm, 128>>>(text, out);
    k_prepW<<<dim3(Dd / 64, Dd / 64), 256>>>(W);
    k_prepfeat<<<dim3(Nn / 64, Dd / 64, Bb), 256>>>(features);
    k_linear<<<dim3(Dd / 128, (Bb * Nn) / 128), 256>>>(bias);
    k_sim<<<dim3(Nn / 128, Mm / 128, Bb), 256>>>();
    k_out<<<dim3(Mm / 128, Dd / 128, Bb), 256>>>(out);
}

// round 13
// speedup vs baseline: 1.1929x; 1.0991x over previous
#include <cuda_runtime.h>
#include <cuda_bf16.h>
#include <math.h>

#define Bb 8
#define Nn 4096
#define Mm 2048
#define Dd 512
typedef unsigned u32;

// ---------------- scratch (bf16 packed words, 16B aligned) ----------------
__device__ __align__(16) u32 g_fh [(size_t)Bb * Nn * (Dd / 2)];  // feat rows bf16
__device__ __align__(16) u32 g_fTh[(size_t)Bb * Dd * (Nn / 2)];  // feat^T bf16
__device__ __align__(16) u32 g_wt [(size_t)Dd * (Dd / 2)];       // W^T rows bf16
__device__ __align__(16) u32 g_tnh[(size_t)Mm * (Dd / 2)];       // tn rows bf16
__device__ __align__(16) u32 g_fnh[(size_t)Bb * Nn * (Dd / 2)];  // f1 (unnormalized) bf16
__device__ __align__(16) u32 g_eth[(size_t)Bb * Mm * (Nn / 2)];  // e^T: [b][m][(n,n+1)]
__device__ float g_s[Bb * Mm];   // softmax denominators
__device__ float g_rn[Bb * Nn];  // per-row |f1|^2

__device__ __forceinline__ u32 pk2(float lo, float hi) {
    __nv_bfloat162 h = __floats2bfloat162_rn(lo, hi);
    return *(u32*)&h;
}
__device__ __forceinline__ u32 s2u(const void* p) {
    return (u32)__cvta_generic_to_shared(p);
}
__device__ __forceinline__ void cpa16(u32 saddr, const void* g) {
    asm volatile("cp.async.cg.shared.global [%0], [%1], 16;" :: "r"(saddr), "l"(g));
}
#define CP_COMMIT asm volatile("cp.async.commit_group;" ::: "memory")
#define CP_WAIT2 asm volatile("cp.async.wait_group 2;" ::: "memory")
__device__ __forceinline__ void ldsm4(u32& r0, u32& r1, u32& r2, u32& r3, u32 addr) {
    asm volatile("ldmatrix.sync.aligned.m8n8.x4.shared.b16 {%0,%1,%2,%3}, [%4];"
                 : "=r"(r0), "=r"(r1), "=r"(r2), "=r"(r3) : "r"(addr));
}
__device__ __forceinline__ void mma_bf16(float& d0, float& d1, float& d2, float& d3,
                                         u32 a0, u32 a1, u32 a2, u32 a3,
                                         u32 b0, u32 b1) {
    asm volatile(
        "mma.sync.aligned.m16n8k16.row.col.f32.bf16.bf16.f32 "
        "{%0,%1,%2,%3}, {%4,%5,%6,%7}, {%8,%9}, {%0,%1,%2,%3};"
        : "+f"(d0), "+f"(d1), "+f"(d2), "+f"(d3)
        : "r"(a0), "r"(a1), "r"(a2), "r"(a3), "r"(b0), "r"(b1));
}

// ---------------- small kernels ----------------
__global__ void k_text(const float* __restrict__ text, float* __restrict__ out) {
    int m = blockIdx.x, tid = threadIdx.x;
    const float4* t1 = (const float4*)(text + (size_t)Mm * Dd + (size_t)m * Dd);
    float4 v = t1[tid];
    float ss = v.x * v.x + v.y * v.y + v.z * v.z + v.w * v.w;
#pragma unroll
    for (int o = 16; o > 0; o >>= 1) ss += __shfl_xor_sync(0xffffffffu, ss, o);
    __shared__ float ws[4];
    if ((tid & 31) == 0) ws[tid >> 5] = ss;
    __syncthreads();
    float inv = 1.f / fmaxf(sqrtf(ws[0] + ws[1] + ws[2] + ws[3]), 1e-8f);
    *(uint2*)(g_tnh + (size_t)m * (Dd / 2) + tid * 2) =
        make_uint2(pk2(v.x * inv, v.y * inv), pk2(v.z * inv, v.w * inv));
#pragma unroll
    for (int b = 0; b < Bb; b++) {
        float4* o = (float4*)(out + ((size_t)(b * Mm + m)) * (2 * Dd) + Dd);
        o[tid] = v;
    }
}

// features -> g_fh (row-major bf16) + g_fTh (transpose-pack)
__global__ void k_prepfeat(const float* __restrict__ feat) {
    __shared__ float sm[64][65];
    int b = blockIdx.z, d0 = blockIdx.y * 64, n0 = blockIdx.x * 64;
    int t = threadIdx.x;
    int lr = t >> 4, lc = (t & 15) * 4;
#pragma unroll
    for (int r = 0; r < 4; r++) {
        int n = n0 + lr + r * 16;
        float4 v = *(const float4*)(feat + ((size_t)b * Nn + n) * Dd + d0 + lc);
        sm[lr + r * 16][lc + 0] = v.x;
        sm[lr + r * 16][lc + 1] = v.y;
        sm[lr + r * 16][lc + 2] = v.z;
        sm[lr + r * 16][lc + 3] = v.w;
        *(uint2*)(g_fh + ((size_t)b * Nn + n) * (Dd / 2) + (d0 + lc) / 2) =
            make_uint2(pk2(v.x, v.y), pk2(v.z, v.w));
    }
    __syncthreads();
    int d = t >> 2, npb = (t & 3) * 8;
    u32 w[8];
#pragma unroll
    for (int j = 0; j < 8; j++)
        w[j] = pk2(sm[2 * (npb + j)][d], sm[2 * (npb + j) + 1][d]);
    u32* dst = g_fTh + ((size_t)b * Dd + d0 + d) * (Nn / 2) + n0 / 2 + npb;
    *(uint4*)dst = make_uint4(w[0], w[1], w[2], w[3]);
    *(uint4*)(dst + 4) = make_uint4(w[4], w[5], w[6], w[7]);
}

// W[d][e] -> g_wt[e][(d,d+1)]; also zeroes g_s / g_rn (16384 threads)
__global__ void k_prepW(const float* __restrict__ W) {
    __shared__ float sm[64][65];
    int d0 = blockIdx.y * 64, e0 = blockIdx.x * 64;
    int t = threadIdx.x;
    int gid = (blockIdx.y * gridDim.x + blockIdx.x) * 256 + t;
    g_rn[gid] = 0.f;
    g_rn[gid + 16384] = 0.f;
    g_s[gid] = 0.f;
    int lr = t >> 4, lc = (t & 15) * 4;
#pragma unroll
    for (int r = 0; r < 4; r++) {
        float4 v = *(const float4*)(W + (size_t)(d0 + lr + r * 16) * Dd + e0 + lc);
        sm[lr + r * 16][lc + 0] = v.x;
        sm[lr + r * 16][lc + 1] = v.y;
        sm[lr + r * 16][lc + 2] = v.z;
        sm[lr + r * 16][lc + 3] = v.w;
    }
    __syncthreads();
    int e = t >> 2, dpb = (t & 3) * 8;
    u32 w[8];
#pragma unroll
    for (int j = 0; j < 8; j++)
        w[j] = pk2(sm[2 * (dpb + j)][e], sm[2 * (dpb + j) + 1][e]);
    u32* dst = g_wt + (size_t)(e0 + e) * (Dd / 2) + d0 / 2 + dpb;
    *(uint4*)dst = make_uint4(w[0], w[1], w[2], w[3]);
    *(uint4*)(dst + 4) = make_uint4(w[4], w[5], w[6], w[7]);
}

// ==== GEMM framework: block 128x256, 256 thr, warp tile 64x64 (R8 champion) ====
// smem rows = 8 words (32B), chunk swizzle: phys = c ^ ((row>>2)&1)
// stage: A 4KB (128 rows) + B 8KB (256 rows); 4 stages, 1 sync/iter, wait 2.

__device__ __forceinline__ void ldA(u32 dst, const u32* src, size_t ldw, int kw, int tid) {
    int r = tid >> 1, c = tid & 1;
    cpa16(dst + (u32)(r * 32 + ((c ^ ((r >> 2) & 1)) * 16)),
          src + (size_t)r * ldw + kw + c * 4);
}
__device__ __forceinline__ void ldB(u32 dst, const u32* src, size_t ldw, int kw, int tid) {
    int r0 = tid >> 1, c = tid & 1;
#pragma unroll
    for (int i = 0; i < 2; i++) {
        int r = r0 + i * 128;
        cpa16(dst + (u32)(r * 32 + ((c ^ ((r >> 2) & 1)) * 16)),
              src + (size_t)r * ldw + kw + c * 4);
    }
}

#define GEMM_DECLS                                                          \
    __shared__ __align__(16) u32 sA[4][1024], sB[4][2048];                  \
    u32 sAu = s2u(sA), sBu = s2u(sB);                                       \
    int tid = threadIdx.x, lane = tid & 31, warp = tid >> 5;                \
    int wm = warp >> 2, wn = warp & 3;                                      \
    int lg = lane >> 2, lt = lane & 3;                                      \
    int rowA = wm * 64 + (lane & 15);                                       \
    u32 aoff = (u32)(rowA * 32 + (((lane >> 4) ^ ((rowA >> 2) & 1)) * 16)); \
    int rowB = wn * 64 + (lane & 7) + ((lane >> 4) << 3);                   \
    u32 boff = (u32)(rowB * 32 + ((((lane >> 3) & 1) ^ ((rowB >> 2) & 1)) * 16)); \
    float acc[4][8][4];                                                     \
    _Pragma("unroll") for (int i = 0; i < 4; i++)                           \
    _Pragma("unroll") for (int j = 0; j < 8; j++)                           \
    _Pragma("unroll") for (int r = 0; r < 4; r++) acc[i][j][r] = 0.f;

#define COMPUTE16(pA, pB) {                                                 \
    u32 af[4][4], bq[4][4];                                                 \
    _Pragma("unroll") for (int mt = 0; mt < 4; mt++)                        \
        ldsm4(af[mt][0], af[mt][1], af[mt][2], af[mt][3],                   \
              sAu + (pA) + aoff + mt * 512);                                \
    _Pragma("unroll") for (int pq = 0; pq < 4; pq++)                        \
        ldsm4(bq[pq][0], bq[pq][1], bq[pq][2], bq[pq][3],                   \
              sBu + (pB) + boff + pq * 512);                                \
    _Pragma("unroll") for (int mt = 0; mt < 4; mt++)                        \
        _Pragma("unroll") for (int nt = 0; nt < 8; nt++)                    \
            mma_bf16(acc[mt][nt][0], acc[mt][nt][1],                        \
                     acc[mt][nt][2], acc[mt][nt][3],                        \
                     af[mt][0], af[mt][1], af[mt][2], af[mt][3],            \
                     bq[nt >> 1][(nt & 1) * 2], bq[nt >> 1][(nt & 1) * 2 + 1]); }

// 4-stage pipeline, single __syncthreads per iter, wait_group 2 (R8 proven).
#define MAINLOOP(Asrc, Aldw, Bsrc, Bldw, S)                                 \
    _Pragma("unroll") for (int st = 0; st < 3; st++) {                      \
        ldA(sAu + st * 4096, (Asrc), (Aldw), st * 8, tid);                  \
        ldB(sBu + st * 8192, (Bsrc), (Bldw), st * 8, tid);                  \
        CP_COMMIT;                                                          \
    }                                                                       \
    for (int s = 0; s < (S); s++) {                                         \
        int p = s & 3;                                                      \
        CP_WAIT2; __syncthreads();                                          \
        COMPUTE16(p * 4096, p * 8192)                                       \
        int f = s + 3;                                                      \
        if (f < (S)) {                                                      \
            int q = f & 3;                                                  \
            ldA(sAu + q * 4096, (Asrc), (Aldw), f * 8, tid);                \
            ldB(sBu + q * 8192, (Bsrc), (Bldw), f * 8, tid);                \
        }                                                                   \
        CP_COMMIT;                                                          \
    }

// ---------------- K2: f1 = feat @ W + b -> g_fnh (+ row |f1|^2) ----------
__global__ __launch_bounds__(256, 1)
void k_linear(const float* __restrict__ bias) {
    GEMM_DECLS
    int m0 = blockIdx.y * 128;  // over B*N
    int e0 = blockIdx.x * 256;  // over Dd
    const u32* Asrc = g_fh + (size_t)m0 * (Dd / 2);
    const u32* Bsrc = g_wt + (size_t)e0 * (Dd / 2);
    MAINLOOP(Asrc, Dd / 2, Bsrc, Dd / 2, 32)
    float rs[4][2];
#pragma unroll
    for (int mt = 0; mt < 4; mt++) { rs[mt][0] = 0.f; rs[mt][1] = 0.f; }
#pragma unroll
    for (int mt = 0; mt < 4; mt++) {
        int row = m0 + wm * 64 + mt * 16 + lg;
#pragma unroll
        for (int nt = 0; nt < 8; nt++) {
            int col = e0 + wn * 64 + nt * 8 + lt * 2;
            float b0 = __ldg(bias + col), b1 = __ldg(bias + col + 1);
            float f0 = acc[mt][nt][0] + b0, f1 = acc[mt][nt][1] + b1;
            float f2 = acc[mt][nt][2] + b0, f3 = acc[mt][nt][3] + b1;
            g_fnh[((size_t)row * Dd + col) >> 1] = pk2(f0, f1);
            g_fnh[((size_t)(row + 8) * Dd + col) >> 1] = pk2(f2, f3);
            rs[mt][0] += f0 * f0 + f1 * f1;
            rs[mt][1] += f2 * f2 + f3 * f3;
        }
    }
#pragma unroll
    for (int mt = 0; mt < 4; mt++)
#pragma unroll
        for (int r = 0; r < 2; r++) {
            float v = rs[mt][r];
            v += __shfl_xor_sync(0xffffffffu, v, 1);
            v += __shfl_xor_sync(0xffffffffu, v, 2);
            if (lt == 0)
                atomicAdd(&g_rn[m0 + wm * 64 + mt * 16 + lg + r * 8], v);
        }
}

// ---------------- K3: e^T = exp(tn @ f1^T * invnorm) -> g_eth; row sums ---
__global__ __launch_bounds__(256, 1)
void k_sim() {
    GEMM_DECLS
    __shared__ float sc[256];
    int b = blockIdx.z;
    int m0 = blockIdx.y * 128;  // over Mm
    int n0 = blockIdx.x * 256;  // over Nn
    const u32* Asrc = g_tnh + (size_t)m0 * (Dd / 2);
    const u32* Bsrc = g_fnh + ((size_t)b * Nn + n0) * (Dd / 2);
    MAINLOOP(Asrc, Dd / 2, Bsrc, Dd / 2, 32)
    sc[tid] = 1.f / fmaxf(sqrtf(g_rn[b * Nn + n0 + tid]), 1e-8f);
    __syncthreads();
    float rs[4][2];
#pragma unroll
    for (int mt = 0; mt < 4; mt++) { rs[mt][0] = 0.f; rs[mt][1] = 0.f; }
#pragma unroll
    for (int mt = 0; mt < 4; mt++) {
        int m = m0 + wm * 64 + mt * 16 + lg;
#pragma unroll
        for (int nt = 0; nt < 8; nt++) {
            int cl = wn * 64 + nt * 8 + lt * 2;  // col within block
            float i0 = sc[cl], i1 = sc[cl + 1];
            float e0 = __expf(acc[mt][nt][0] * i0);
            float e1 = __expf(acc[mt][nt][1] * i1);
            float e2 = __expf(acc[mt][nt][2] * i0);
            float e3 = __expf(acc[mt][nt][3] * i1);
            int nw = (n0 + cl) >> 1;
            g_eth[((size_t)b * Mm + m) * (Nn / 2) + nw] = pk2(e0, e1);
            g_eth[((size_t)b * Mm + m + 8) * (Nn / 2) + nw] = pk2(e2, e3);
            rs[mt][0] += e0 + e1;
            rs[mt][1] += e2 + e3;
        }
    }
#pragma unroll
    for (int mt = 0; mt < 4; mt++)
#pragma unroll
        for (int r = 0; r < 2; r++) {
            float v = rs[mt][r];
            v += __shfl_xor_sync(0xffffffffu, v, 1);
            v += __shfl_xor_sync(0xffffffffu, v, 2);
            if (lt == 0)
                atomicAdd(&g_s[b * Mm + m0 + wm * 64 + mt * 16 + lg + r * 8], v);
        }
}

// ---------------- K4: out[...,:512] = (e @ feat) / s ----------------------
__global__ __launch_bounds__(256, 1)
void k_out(float* __restrict__ out) {
    GEMM_DECLS
    int b = blockIdx.z;
    int m0 = blockIdx.x * 128;  // over Mm (m fastest: concurrent CTAs share B in L2)
    int d0 = blockIdx.y * 256;  // over Dd
    const u32* Asrc = g_eth + ((size_t)b * Mm + m0) * (Nn / 2);
    const u32* Bsrc = g_fTh + ((size_t)b * Dd + d0) * (Nn / 2);
    MAINLOOP(Asrc, Nn / 2, Bsrc, Nn / 2, Nn / 16)
#pragma unroll
    for (int mt = 0; mt < 4; mt++) {
        int row = m0 + wm * 64 + mt * 16 + lg;
        float i0 = 1.f / g_s[b * Mm + row];
        float i1 = 1.f / g_s[b * Mm + row + 8];
#pragma unroll
        for (int nt = 0; nt < 8; nt++) {
            int col = d0 + wn * 64 + nt * 8 + lt * 2;
            *(float2*)(out + ((size_t)(b * Mm + row)) * (2 * Dd) + col) =
                make_float2(acc[mt][nt][0] * i0, acc[mt][nt][1] * i0);
            *(float2*)(out + ((size_t)(b * Mm + row + 8)) * (2 * Dd) + col) =
                make_float2(acc[mt][nt][2] * i1, acc[mt][nt][3] * i1);
        }
    }
}

// ---------------- launch ----------------
extern "C" void kernel_launch(void* const* d_in, const int* in_sizes, int n_in,
                              void* d_out, int out_size) {
    const float* features = (const float*)d_in[0];
    const float* text     = (const float*)d_in[1];
    const float* W        = (const float*)d_in[2];
    const float* bias     = (const float*)d_in[3];
    float* out = (float*)d_out;

    k_text<<<Mm, 128>>>(text, out);
    k_prepW<<<dim3(Dd / 64, Dd / 64), 256>>>(W);
    k_prepfeat<<<dim3(Nn / 64, Dd / 64, Bb), 256>>>(features);
    k_linear<<<dim3(Dd / 256, (Bb * Nn) / 128), 256>>>(bias);
    k_sim<<<dim3(Nn / 256, Mm / 128, Bb), 256>>>();
    k_out<<<dim3(Mm / 128, Dd / 256, Bb), 256>>>(out);
}